// round 1
// baseline (speedup 1.0000x reference)
#include <cuda_runtime.h>
#include <cuda_bf16.h>
#include <math.h>

// SGNS loss:
//   iv = emb_i[iword]                      [B, D]
//   ov = emb_o[owords], nv = emb_o[nwords]
//   oscore = <ov, iv>, nscore = -<nv, iv>
//   loss = -( mean_c logsig(oscore) + mean_c sum_negs logsig(nscore) ).mean_b
//
// Shapes (fixed by the problem):
#define VOCAB 100000
#define DIM   128
#define BATCH 4096
#define CCTX  10
#define NNEG  200              // C * N_NEGS
#define TOTALW (CCTX + NNEG)   // 210 words per batch row

#define NWARPS 8               // warps per block
#define THREADS (NWARPS * 32)

// Deterministic scratch: per-row partial loss (no float atomics anywhere).
__device__ float g_partial[BATCH];

__device__ __forceinline__ float log_sigmoid(float x) {
    // stable: logsig(x) = min(x,0) - log1p(exp(-|x|))
    return fminf(x, 0.0f) - log1pf(__expf(-fabsf(x)));
}

__global__ void __launch_bounds__(THREADS)
sgns_row_kernel(const float* __restrict__ emb_i,
                const float* __restrict__ emb_o,
                const int*   __restrict__ iword,
                const int*   __restrict__ owords,
                const int*   __restrict__ nwords)
{
    const int b    = blockIdx.x;
    const int lane = threadIdx.x & 31;
    const int warp = threadIdx.x >> 5;

    __shared__ float s_iv[DIM];
    __shared__ float s_wsum[NWARPS];

    // Load the input-word embedding row into shared (coalesced, 128 floats).
    if (threadIdx.x < DIM) {
        const size_t irow = (size_t)iword[b] * DIM;
        s_iv[threadIdx.x] = emb_i[irow + threadIdx.x];
    }
    __syncthreads();

    // Each lane holds 4 consecutive floats of iv -> a warp covers all 128.
    const float4 ivr = *reinterpret_cast<const float4*>(&s_iv[lane * 4]);

    const int* __restrict__ orow = owords + (size_t)b * CCTX;
    const int* __restrict__ nrow = nwords + (size_t)b * NNEG;

    float acc = 0.0f;

    // Warp w handles words w, w+NWARPS, ... of the 210 (10 pos + 200 neg).
    // 2-way manual pipelining: issue the next row's index load early by
    // iterating two words per trip (stride 2*NWARPS) for MLP.
    for (int w = warp; w < TOTALW; w += NWARPS) {
        int idx;
        float sign;
        if (w < CCTX) { idx = orow[w];        sign =  1.0f; }
        else          { idx = nrow[w - CCTX]; sign = -1.0f; }

        const float4 ev = *reinterpret_cast<const float4*>(
            emb_o + (size_t)idx * DIM + lane * 4);

        float d = fmaf(ivr.x, ev.x,
                  fmaf(ivr.y, ev.y,
                  fmaf(ivr.z, ev.z, ivr.w * ev.w)));

        // butterfly reduce: all lanes end with the full 128-wide dot
        #pragma unroll
        for (int o = 16; o > 0; o >>= 1)
            d += __shfl_xor_sync(0xFFFFFFFFu, d, o);

        acc += log_sigmoid(sign * d);
    }

    if (lane == 0) s_wsum[warp] = acc;
    __syncthreads();

    if (threadIdx.x == 0) {
        float s = 0.0f;
        #pragma unroll
        for (int i = 0; i < NWARPS; i++) s += s_wsum[i];
        // per-row value: (oloss.mean(1) + nloss.mean(1)) = total_sum / C
        g_partial[b] = s * (1.0f / CCTX);
    }
}

__global__ void __launch_bounds__(256)
sgns_reduce_kernel(float* __restrict__ out)
{
    __shared__ float sm[256];
    float s = 0.0f;
    for (int i = threadIdx.x; i < BATCH; i += 256)
        s += g_partial[i];
    sm[threadIdx.x] = s;
    __syncthreads();
    #pragma unroll
    for (int st = 128; st > 0; st >>= 1) {
        if (threadIdx.x < st) sm[threadIdx.x] += sm[threadIdx.x + st];
        __syncthreads();
    }
    if (threadIdx.x == 0)
        out[0] = -sm[0] * (1.0f / BATCH);
}

extern "C" void kernel_launch(void* const* d_in, const int* in_sizes, int n_in,
                              void* d_out, int out_size)
{
    const float* emb_i  = (const float*)d_in[0];
    const float* emb_o  = (const float*)d_in[1];
    const int*   iword  = (const int*)  d_in[2];
    const int*   owords = (const int*)  d_in[3];
    const int*   nwords = (const int*)  d_in[4];
    float*       out    = (float*)      d_out;

    const int B = in_sizes[2];  // 4096

    sgns_row_kernel<<<B, THREADS>>>(emb_i, emb_o, iword, owords, nwords);
    sgns_reduce_kernel<<<1, 256>>>(out);
}

// round 2
// speedup vs baseline: 1.0908x; 1.0908x over previous
#include <cuda_runtime.h>
#include <cuda_bf16.h>
#include <math.h>

// SGNS loss, fused single-kernel version.
//   iv = emb_i[iword]; ov/nv = emb_o[owords/nwords]
//   loss = -( mean_c logsig(<ov,iv>) + mean_c sum_negs logsig(-<nv,iv>) ).mean_b

#define VOCAB 100000
#define DIM   128
#define BATCH 4096
#define CCTX  10
#define NNEG  200              // C * N_NEGS
#define TOTALW (CCTX + NNEG)   // 210 words per row

#define NWARPS 8
#define THREADS (NWARPS * 32)

__device__ float        g_partial[BATCH];
__device__ unsigned int g_count = 0;   // deterministically reset by last block

__device__ __forceinline__ float log_sigmoid(float x) {
    return fminf(x, 0.0f) - log1pf(__expf(-fabsf(x)));
}

__device__ __forceinline__ float dot4(float4 a, float4 b) {
    return fmaf(a.x, b.x, fmaf(a.y, b.y, fmaf(a.z, b.z, a.w * b.w)));
}

__global__ void __launch_bounds__(THREADS)
sgns_fused_kernel(const float* __restrict__ emb_i,
                  const float* __restrict__ emb_o,
                  const int*   __restrict__ iword,
                  const int*   __restrict__ owords,
                  const int*   __restrict__ nwords,
                  float*       __restrict__ out)
{
    const int b    = blockIdx.x;
    const int lane = threadIdx.x & 31;
    const int warp = threadIdx.x >> 5;

    __shared__ float s_iv[DIM];
    __shared__ float s_wsum[NWARPS];

    if (threadIdx.x < DIM) {
        const size_t irow = (size_t)iword[b] * DIM;
        s_iv[threadIdx.x] = emb_i[irow + threadIdx.x];
    }
    __syncthreads();

    // Each lane owns 4 consecutive floats of iv.
    const float4 ivr = *reinterpret_cast<const float4*>(&s_iv[lane * 4]);

    const int* __restrict__ orow = owords + (size_t)b * CCTX;
    const int* __restrict__ nrow = nwords + (size_t)b * NNEG;

    float acc = 0.0f;

    // 4-way unrolled stride loop: 4 independent row loads in flight (MLP=4),
    // 4 interleaved butterfly reductions so SHFL latencies overlap.
    int w = warp;
    for (; w + 3 * NWARPS < TOTALW; w += 4 * NWARPS) {
        int   idx[4];
        float sgn[4];
        #pragma unroll
        for (int u = 0; u < 4; u++) {
            int ww = w + u * NWARPS;
            if (ww < CCTX) { idx[u] = orow[ww];        sgn[u] =  1.0f; }
            else           { idx[u] = nrow[ww - CCTX]; sgn[u] = -1.0f; }
        }

        float4 ev0 = *reinterpret_cast<const float4*>(emb_o + (size_t)idx[0] * DIM + lane * 4);
        float4 ev1 = *reinterpret_cast<const float4*>(emb_o + (size_t)idx[1] * DIM + lane * 4);
        float4 ev2 = *reinterpret_cast<const float4*>(emb_o + (size_t)idx[2] * DIM + lane * 4);
        float4 ev3 = *reinterpret_cast<const float4*>(emb_o + (size_t)idx[3] * DIM + lane * 4);

        float d0 = dot4(ivr, ev0);
        float d1 = dot4(ivr, ev1);
        float d2 = dot4(ivr, ev2);
        float d3 = dot4(ivr, ev3);

        #pragma unroll
        for (int o = 16; o > 0; o >>= 1) {
            d0 += __shfl_xor_sync(0xFFFFFFFFu, d0, o);
            d1 += __shfl_xor_sync(0xFFFFFFFFu, d1, o);
            d2 += __shfl_xor_sync(0xFFFFFFFFu, d2, o);
            d3 += __shfl_xor_sync(0xFFFFFFFFu, d3, o);
        }

        acc += log_sigmoid(sgn[0] * d0);
        acc += log_sigmoid(sgn[1] * d1);
        acc += log_sigmoid(sgn[2] * d2);
        acc += log_sigmoid(sgn[3] * d3);
    }
    // remainder (≤3 words per warp)
    for (; w < TOTALW; w += NWARPS) {
        int   idx;
        float sgn;
        if (w < CCTX) { idx = orow[w];        sgn =  1.0f; }
        else          { idx = nrow[w - CCTX]; sgn = -1.0f; }

        float4 ev = *reinterpret_cast<const float4*>(emb_o + (size_t)idx * DIM + lane * 4);
        float d = dot4(ivr, ev);
        #pragma unroll
        for (int o = 16; o > 0; o >>= 1)
            d += __shfl_xor_sync(0xFFFFFFFFu, d, o);
        acc += log_sigmoid(sgn * d);
    }

    if (lane == 0) s_wsum[warp] = acc;
    __syncthreads();

    // ---- fused final reduction: last block to finish sums g_partial ----
    __shared__ bool s_last;
    if (threadIdx.x == 0) {
        float s = 0.0f;
        #pragma unroll
        for (int i = 0; i < NWARPS; i++) s += s_wsum[i];
        g_partial[b] = s * (1.0f / CCTX);
        __threadfence();
        unsigned prev = atomicAdd(&g_count, 1u);
        s_last = (prev == (unsigned)(BATCH - 1));
    }
    __syncthreads();

    if (s_last) {
        // All other blocks' g_partial writes are visible (fence + atomic order).
        __shared__ float sm[THREADS];
        float s = 0.0f;
        for (int i = threadIdx.x; i < BATCH; i += THREADS)
            s += g_partial[i];
        sm[threadIdx.x] = s;
        __syncthreads();
        #pragma unroll
        for (int st = THREADS / 2; st > 0; st >>= 1) {
            if (threadIdx.x < st) sm[threadIdx.x] += sm[threadIdx.x + st];
            __syncthreads();
        }
        if (threadIdx.x == 0) {
            out[0] = -sm[0] * (1.0f / BATCH);
            g_count = 0;   // reset for next graph replay (deterministic)
        }
    }
}

extern "C" void kernel_launch(void* const* d_in, const int* in_sizes, int n_in,
                              void* d_out, int out_size)
{
    const float* emb_i  = (const float*)d_in[0];
    const float* emb_o  = (const float*)d_in[1];
    const int*   iword  = (const int*)  d_in[2];
    const int*   owords = (const int*)  d_in[3];
    const int*   nwords = (const int*)  d_in[4];
    float*       out    = (float*)      d_out;

    const int B = in_sizes[2];  // 4096

    sgns_fused_kernel<<<B, THREADS>>>(emb_i, emb_o, iword, owords, nwords, out);
}